// round 3
// baseline (speedup 1.0000x reference)
#include <cuda_runtime.h>
#include <math.h>

#define NNODES 2048

__constant__ float c_fact[16] = {
    1.f, 1.f, 2.f, 6.f, 24.f, 120.f, 720.f, 5040.f, 40320.f, 362880.f,
    3628800.f, 39916800.f, 479001600.f, 6227020800.f, 87178291200.f, 1307674368000.f};

struct DevConsts {
    float cg[576];   // 13 path CG tensors concatenated (573 used)
    float rec1[45];  // w3j(1,1,2)
    float rec2[105]; // w3j(2,1,3)
    float sh_s0, sh_s1, silu_c;
};
__device__ DevConsts g_c;

__device__ __align__(16) float g_node_sum[NNODES * 1024]; // 8 MB scatter buffer
__device__ __align__(16) float g_W0T[8192];
__device__ __align__(16) float g_W1T[20480];
__device__ __align__(16) float g_W2T[4096];
__device__ __align__(16) float g_W3T[4096];

// ---------------------------------------------------------------------------
// device-side e3nn constants (Wigner 3j in real basis, SH scales, silu norm)
// ---------------------------------------------------------------------------
__device__ float su2_cg(int j1, int m1, int j2, int m2, int j3, int m3) {
    if (m1 + m2 != m3) return 0.f;
    int vmin = max(max(-j1 + j2 + m3, -j1 + m1), 0);
    int vmax = min(min(j2 + j3 + m1, j3 - j1 + j2), j3 + m3);
    float c = sqrtf((2.f * j3 + 1.f) * c_fact[j3 + j1 - j2] * c_fact[j3 - j1 + j2] *
                    c_fact[j1 + j2 - j3] / c_fact[j1 + j2 + j3 + 1] *
                    c_fact[j3 + m3] * c_fact[j3 - m3] /
                    (c_fact[j1 + m1] * c_fact[j1 - m1] * c_fact[j2 + m2] * c_fact[j2 - m2]));
    float s = 0.f;
    for (int v = vmin; v <= vmax; v++) {
        float t = c_fact[j2 + j3 + m1 - v] * c_fact[j1 - m1 + v] /
                  (c_fact[v] * c_fact[j3 - j1 + j2 - v] * c_fact[j3 + m3 - v] *
                   c_fact[v + j1 - j2 - m3]);
        s += ((v + j2 + m2) & 1) ? -t : t;
    }
    return c * s;
}

__device__ void build_q(int l, float2* q) {
    int d = 2 * l + 1;
    for (int i = 0; i < d * d; i++) q[i] = make_float2(0.f, 0.f);
    const float r = 0.7071067811865476f;
    for (int m = -l; m < 0; m++) {
        q[(l + m) * d + (l - m)] = make_float2(r, 0.f);
        q[(l + m) * d + (l + m)] = make_float2(0.f, -r);
    }
    q[l * d + l] = make_float2(1.f, 0.f);
    for (int m = 1; m <= l; m++) {
        float sg = (m & 1) ? -1.f : 1.f;
        q[(l + m) * d + (l + m)] = make_float2(sg * r, 0.f);
        q[(l + m) * d + (l - m)] = make_float2(0.f, sg * r);
    }
    float2 ph;
    switch (l & 3) {  // (-i)^l
        case 0: ph = make_float2(1.f, 0.f); break;
        case 1: ph = make_float2(0.f, -1.f); break;
        case 2: ph = make_float2(-1.f, 0.f); break;
        default: ph = make_float2(0.f, 1.f); break;
    }
    for (int i = 0; i < d * d; i++) {
        float2 a = q[i];
        q[i] = make_float2(a.x * ph.x - a.y * ph.y, a.x * ph.y + a.y * ph.x);
    }
}

__global__ void init_consts_kernel() {
    __shared__ float Cr[125];
    __shared__ float outs[125];
    __shared__ float2 q1s[49], q2s[49], q3s[49];
    __shared__ float red[256];
    int tid = threadIdx.x;
    const int NT = 14;
    const int tl1[NT] = {0, 1, 2, 0, 1, 1, 2, 3, 0, 1, 2, 2, 3, 2};
    const int tl2[NT] = {0, 1, 2, 1, 0, 2, 1, 2, 2, 1, 0, 2, 1, 1};
    const int tl3[NT] = {0, 0, 0, 1, 1, 1, 1, 1, 2, 2, 2, 2, 2, 3};
    const int toff[NT] = {0, 1, 10, 35, 44, 53, 98, 143, 248, 273, 318, 343, 468, 0};

    for (int t = 0; t < NT; t++) {
        int l1 = tl1[t], l2 = tl2[t], l3 = tl3[t];
        int d1 = 2 * l1 + 1, d2 = 2 * l2 + 1, d3 = 2 * l3 + 1;
        int sz = d1 * d2 * d3;
        for (int idx = tid; idx < sz; idx += blockDim.x) {
            int i = idx / (d2 * d3), rr = idx % (d2 * d3), k = rr / d3, m = rr % d3;
            Cr[idx] = su2_cg(l1, i - l1, l2, k - l2, l3, m - l3);
        }
        if (tid == 0) build_q(l1, q1s);
        else if (tid == 1) build_q(l2, q2s);
        else if (tid == 2) build_q(l3, q3s);
        __syncthreads();
        float ss = 0.f;
        for (int idx = tid; idx < sz; idx += blockDim.x) {
            int j = idx / (d2 * d3), rr = idx % (d2 * d3), lc = rr / d3, n = rr % d3;
            float re = 0.f;
            for (int i = 0; i < d1; i++) {
                float2 a = q1s[i * d1 + j];
                for (int k = 0; k < d2; k++) {
                    float2 b = q2s[k * d2 + lc];
                    float abr = a.x * b.x - a.y * b.y;
                    float abi = a.x * b.y + a.y * b.x;
                    for (int m = 0; m < d3; m++) {
                        float cv = Cr[(i * d2 + k) * d3 + m];
                        if (cv == 0.f) continue;
                        float2 g = q3s[m * d3 + n]; // conj(g)
                        re += cv * (abr * g.x + abi * g.y);
                    }
                }
            }
            outs[idx] = re;
            ss += re * re;
        }
        red[tid] = ss;
        __syncthreads();
        for (int st = 128; st > 0; st >>= 1) {
            if (tid < st) red[tid] += red[tid + st];
            __syncthreads();
        }
        float inv = rsqrtf(red[0]);
        for (int idx = tid; idx < sz; idx += blockDim.x) {
            float v = outs[idx] * inv;
            if (t == 13) g_c.rec2[idx] = v;
            else {
                g_c.cg[toff[t] + idx] = v;
                if (l1 == 1 && l2 == 1 && l3 == 2) g_c.rec1[idx] = v;
            }
        }
        __syncthreads();
    }

    if (tid == 0) {
        float n0 = 0.3f, n1 = 0.5f, n2 = 0.81f;
        float inv = rsqrtf(n0 * n0 + n1 * n1 + n2 * n2);
        float ny[3] = {n1 * inv, n2 * inv, n0 * inv};
        float Y1[3];
        for (int i = 0; i < 3; i++) Y1[i] = 1.7320508075688772f * ny[i];
        float A[5] = {0, 0, 0, 0, 0};
        for (int i = 0; i < 3; i++)
            for (int j = 0; j < 3; j++) {
                float tt = Y1[i] * ny[j];
                for (int k = 0; k < 5; k++) A[k] += tt * g_c.rec1[(i * 3 + j) * 5 + k];
            }
        float na = 0.f;
        for (int k = 0; k < 5; k++) na += A[k] * A[k];
        float s0 = sqrtf(5.f) * rsqrtf(na);
        g_c.sh_s0 = s0;
        float Y2[5];
        for (int k = 0; k < 5; k++) Y2[k] = A[k] * s0;
        float B[7] = {0, 0, 0, 0, 0, 0, 0};
        for (int i = 0; i < 5; i++)
            for (int j = 0; j < 3; j++) {
                float tt = Y2[i] * ny[j];
                for (int k = 0; k < 7; k++) B[k] += tt * g_c.rec2[(i * 3 + j) * 7 + k];
            }
        float nb = 0.f;
        for (int k = 0; k < 7; k++) nb += B[k] * B[k];
        g_c.sh_s1 = sqrtf(7.f) * rsqrtf(nb);
    }

    // silu normalization: trapz over [-12,12], 20001 pts (err << 1e-4)
    float part = 0.f;
    for (int i = tid; i < 20001; i += blockDim.x) {
        float z = -12.f + 24.f * (float)i / 20000.f;
        float s = z / (1.f + expf(-z));
        float phi = expf(-0.5f * z * z) * 0.3989422804014327f;
        float w = (i == 0 || i == 20000) ? 0.5f : 1.f;
        part += w * s * s * phi;
    }
    red[tid] = part;
    __syncthreads();
    for (int st = 128; st > 0; st >>= 1) {
        if (tid < st) red[tid] += red[tid + st];
        __syncthreads();
    }
    if (tid == 0) g_c.silu_c = rsqrtf(red[0] * (24.f / 20000.f));
}

// ---------------------------------------------------------------------------
__global__ void zero_nodesum_kernel() {
    int i = blockIdx.x * blockDim.x + threadIdx.x;
    ((float4*)g_node_sum)[i] = make_float4(0.f, 0.f, 0.f, 0.f);
}

// W*T[(k/4)*256 + u*4 + k%4] = W[k*64 + u]
__global__ void prep_weights_kernel(const float* __restrict__ W0, const float* __restrict__ W1,
                                    const float* __restrict__ W2, const float* __restrict__ W3) {
    int i = blockIdx.x * blockDim.x + threadIdx.x;
    if (i < 8192)  { int k4 = i >> 8, rm = i & 255, u = rm >> 2, r = rm & 3; g_W0T[i] = W0[(k4 * 4 + r) * 64 + u]; return; }
    i -= 8192;
    if (i < 20480) { int k4 = i >> 8, rm = i & 255, u = rm >> 2, r = rm & 3; g_W1T[i] = W1[(k4 * 4 + r) * 64 + u]; return; }
    i -= 20480;
    if (i < 4096)  { int k4 = i >> 8, rm = i & 255, u = rm >> 2, r = rm & 3; g_W2T[i] = W2[(k4 * 4 + r) * 64 + u]; return; }
    i -= 4096;
    if (i < 4096)  { int k4 = i >> 8, rm = i & 255, u = rm >> 2, r = rm & 3; g_W3T[i] = W3[(k4 * 4 + r) * 64 + u]; }
}

// ---------------------------------------------------------------------------
// K1: w = x@W0/sqrt(128), Y via recursion, scatter w⊗Y into g_node_sum
// ---------------------------------------------------------------------------
__global__ void __launch_bounds__(256) k1_scatter(const float* __restrict__ vectors,
                                                  const float* __restrict__ x,
                                                  const int* __restrict__ senders) {
    __shared__ __align__(16) float xs[4][128];
    __shared__ float ws[4][64];
    __shared__ float Ys[4][16];
    int tid = threadIdx.x, sub = tid >> 6, ut = tid & 63;
    int e = blockIdx.x * 4 + sub;
    xs[sub][ut] = x[(size_t)e * 128 + ut];
    xs[sub][ut + 64] = x[(size_t)e * 128 + 64 + ut];
    __syncthreads();
    float acc = 0.f;
#pragma unroll
    for (int k4 = 0; k4 < 32; k4++) {
        float4 w = *(const float4*)&g_W0T[k4 * 256 + ut * 4];
        float4 xv = ((const float4*)xs[sub])[k4];
        acc += w.x * xv.x + w.y * xv.y + w.z * xv.z + w.w * xv.w;
    }
    ws[sub][ut] = acc * 0.08838834764831845f;
    if (ut == 0) {
        float vx = vectors[3 * e], vy = vectors[3 * e + 1], vz = vectors[3 * e + 2];
        float inv = rsqrtf(vx * vx + vy * vy + vz * vz);
        float ny[3] = {vy * inv, vz * inv, vx * inv};
        Ys[sub][0] = 1.f;
        float Y1[3];
#pragma unroll
        for (int i = 0; i < 3; i++) { Y1[i] = 1.7320508075688772f * ny[i]; Ys[sub][1 + i] = Y1[i]; }
        float Y2[5] = {0, 0, 0, 0, 0};
        for (int i = 0; i < 3; i++)
            for (int j = 0; j < 3; j++) {
                float t = Y1[i] * ny[j];
#pragma unroll
                for (int k = 0; k < 5; k++) Y2[k] += t * g_c.rec1[(i * 3 + j) * 5 + k];
            }
        float s0 = g_c.sh_s0;
#pragma unroll
        for (int k = 0; k < 5; k++) { Y2[k] *= s0; Ys[sub][4 + k] = Y2[k]; }
        float Y3[7] = {0, 0, 0, 0, 0, 0, 0};
        for (int i = 0; i < 5; i++)
            for (int j = 0; j < 3; j++) {
                float t = Y2[i] * ny[j];
#pragma unroll
                for (int k = 0; k < 7; k++) Y3[k] += t * g_c.rec2[(i * 3 + j) * 7 + k];
            }
        float s1 = g_c.sh_s1;
#pragma unroll
        for (int k = 0; k < 7; k++) Ys[sub][9 + k] = Y3[k] * s1;
    }
    __syncthreads();
    int s = senders[e];
    float* np = g_node_sum + (size_t)s * 1024;
#pragma unroll
    for (int g = 0; g < 4; g++) {
        int base = ut * 4 + g * 256;
        int uu = base >> 4, i0 = base & 15;
        float w = ws[sub][uu];
        atomicAdd((float4*)(np + base),
                  make_float4(w * Ys[sub][i0], w * Ys[sub][i0 + 1], w * Ys[sub][i0 + 2], w * Ys[sub][i0 + 3]));
    }
}

// ---------------------------------------------------------------------------
// K2 helpers
// ---------------------------------------------------------------------------
template <int L1, int L2, int L3, int OFF, int GRP, int PI>
__device__ __forceinline__ void tp_path(const float* __restrict__ cgs, const float* wr,
                                        const float* vr, float* v8, float* x2dst, int u) {
    const int d1 = 2 * L1 + 1, d2 = 2 * L2 + 1, d3 = 2 * L3 + 1;
#pragma unroll
    for (int k = 0; k < d3; k++) {
        float a = 0.f;
#pragma unroll
        for (int i = 0; i < d1; i++)
#pragma unroll
            for (int j = 0; j < d2; j++)
                a += cgs[OFF + (i * d2 + j) * d3 + k] * wr[L1 * L1 + i] * vr[L2 * L2 + j];
        if (GRP == 0) x2dst[u * 3 + PI] = a;
        else if (GRP == 1) v8[(u * 5 + PI) * 8 + k] = 1.7320508075688772f * a;
        else v8[(u * 5 + PI) * 8 + 3 + k] = 2.2360679774997896f * a;
    }
}

__device__ __forceinline__ float silu_n(float z, float c) {
    return z * c / (1.f + __expf(-z));
}

#define K2_SMEM 214304

// ---------------------------------------------------------------------------
// K2: gather + tensor product + scalar MLP + equivariant linear (fused)
// ---------------------------------------------------------------------------
__global__ void __launch_bounds__(256, 1) k2_main(
    const float* __restrict__ vectors, const float* __restrict__ x,
    const float* __restrict__ V, const int* __restrict__ senders,
    const float* __restrict__ Wl1, const float* __restrict__ Wl2,
    float* __restrict__ xout, float* __restrict__ Vout) {
    extern __shared__ __align__(16) float sm[];
    float* Wl1s = sm;            // 20480
    float* Wl2s = Wl1s + 20480;  // 20480
    float* cgs = Wl2s + 20480;   // 576
    float* wYs = cgs + 576;      // 1024
    float* Vcs = wYs + 1024;     // 768 (64 x 12 padded)
    float* v8 = Vcs + 768;       // 2560 (320 x 8)
    float* opart = v8 + 2560;    // 4096 (8 x 512)
    float* x2b = opart + 4096;   // 2560 (8 x 320)
    float* h1b = x2b + 2560;     // 512
    float* h2b = h1b + 512;      // 512
    float* envb = h2b + 512;     // 8

    int tid = threadIdx.x;
    // stage weights in shared
    for (int t = tid; t < 5120; t += 256) ((float4*)Wl1s)[t] = ((const float4*)Wl1)[t];
    for (int t = tid; t < 5120; t += 256) ((float4*)Wl2s)[t] = ((const float4*)Wl2)[t];
    for (int t = tid; t < 573; t += 256) cgs[t] = g_c.cg[t];
    float silu_c = g_c.silu_c;
    __syncthreads();

    int e_base = blockIdx.x * 32;
    int u = tid & 63, pg = tid >> 6;          // phase B mapping
    int u2 = tid & 31, part = tid >> 5;       // phase D mapping

    for (int b8 = 0; b8 < 4; b8++) {
        int e0 = e_base + b8 * 8;
        for (int eb = 0; eb < 8; eb++) {
            int e = e0 + eb;
            __syncthreads();
            // ---- A: load ----
            {
                int s = senders[e];
                float4 v = ((const float4*)(g_node_sum + (size_t)s * 1024))[tid];
                v.x *= 0.25f; v.y *= 0.25f; v.z *= 0.25f; v.w *= 0.25f;
                ((float4*)wYs)[tid] = v;
                for (int t = tid; t < 576; t += 256)
                    Vcs[(t / 9) * 12 + (t % 9)] = V[(size_t)e * 576 + t];
                if (tid < 32)
                    ((float4*)(x2b + eb * 320))[tid] = ((const float4*)(x + (size_t)e * 128))[tid];
                if (tid == 0) {
                    float vx = vectors[3 * e], vy = vectors[3 * e + 1], vz = vectors[3 * e + 2];
                    float d = sqrtf(vx * vx + vy * vy + vz * vz);
                    float d3 = d * d * d, d6 = d3 * d3;
                    envb[eb] = (d < 1.f) ? 1.f + d6 * (-28.f + d * (48.f - 21.f * d)) : 0.f;
                }
            }
            __syncthreads();
            // ---- B: tensor product ----
            {
                float wr[16], vr[9];
#pragma unroll
                for (int t = 0; t < 16; t++) wr[t] = wYs[u * 16 + t];
#pragma unroll
                for (int t = 0; t < 9; t++) vr[t] = Vcs[u * 12 + t];
                float* x2dst = x2b + eb * 320 + 128;
                if (pg == 0) {
                    tp_path<2, 2, 2, 343, 2, 3>(cgs, wr, vr, v8, x2dst, u);
                    tp_path<0, 0, 0, 0, 0, 0>(cgs, wr, vr, v8, x2dst, u);
                    tp_path<0, 1, 1, 35, 1, 0>(cgs, wr, vr, v8, x2dst, u);
                } else if (pg == 1) {
                    tp_path<3, 2, 1, 143, 1, 4>(cgs, wr, vr, v8, x2dst, u);
                    tp_path<1, 2, 1, 53, 1, 2>(cgs, wr, vr, v8, x2dst, u);
                } else if (pg == 2) {
                    tp_path<3, 1, 2, 468, 2, 4>(cgs, wr, vr, v8, x2dst, u);
                    tp_path<2, 1, 1, 98, 1, 3>(cgs, wr, vr, v8, x2dst, u);
                } else {
                    tp_path<0, 2, 2, 248, 2, 0>(cgs, wr, vr, v8, x2dst, u);
                    tp_path<2, 2, 0, 10, 0, 2>(cgs, wr, vr, v8, x2dst, u);
                    tp_path<2, 0, 2, 318, 2, 2>(cgs, wr, vr, v8, x2dst, u);
                    tp_path<1, 1, 2, 273, 2, 1>(cgs, wr, vr, v8, x2dst, u);
                    tp_path<1, 1, 0, 1, 0, 1>(cgs, wr, vr, v8, x2dst, u);
                    tp_path<1, 0, 1, 44, 1, 1>(cgs, wr, vr, v8, x2dst, u);
                }
            }
            __syncthreads();
            // ---- D: equivariant linear (weights in smem) ----
            {
                float a0[8] = {0, 0, 0, 0, 0, 0, 0, 0};
                float a1[8] = {0, 0, 0, 0, 0, 0, 0, 0};
                int m0 = part * 40;
#pragma unroll 2
                for (int m = m0; m < m0 + 40; m++) {
                    float2 w1 = *(const float2*)&Wl1s[m * 64 + 2 * u2];
                    float2 w2 = *(const float2*)&Wl2s[m * 64 + 2 * u2];
                    float4 va = *(const float4*)&v8[m * 8];
                    float4 vb = *(const float4*)&v8[m * 8 + 4];
                    a0[0] += va.x * w1.x; a1[0] += va.x * w1.y;
                    a0[1] += va.y * w1.x; a1[1] += va.y * w1.y;
                    a0[2] += va.z * w1.x; a1[2] += va.z * w1.y;
                    a0[3] += va.w * w2.x; a1[3] += va.w * w2.y;
                    a0[4] += vb.x * w2.x; a1[4] += vb.x * w2.y;
                    a0[5] += vb.y * w2.x; a1[5] += vb.y * w2.y;
                    a0[6] += vb.z * w2.x; a1[6] += vb.z * w2.y;
                    a0[7] += vb.w * w2.x; a1[7] += vb.w * w2.y;
                }
                float* op = opart + part * 512;
                int uu = 2 * u2;
#pragma unroll
                for (int i = 0; i < 3; i++) { op[i * 64 + uu] = a0[i]; op[i * 64 + uu + 1] = a1[i]; }
#pragma unroll
                for (int i = 0; i < 5; i++) { op[192 + i * 64 + uu] = a0[3 + i]; op[192 + i * 64 + uu + 1] = a1[3 + i]; }
            }
            __syncthreads();
            // ---- reduce + write V_out ----
            {
#pragma unroll
                for (int oid = tid; oid < 512; oid += 256) {
                    float s = 0.f;
#pragma unroll
                    for (int p = 0; p < 8; p++) s += opart[p * 512 + oid];
                    s *= 0.05590169943749474f; // 1/sqrt(320)
                    int col;
                    if (oid < 192) { int i = oid >> 6, uu = oid & 63; col = 64 + uu * 3 + i; }
                    else { int o2 = oid - 192; int i = o2 >> 6, uu = o2 & 63; col = 256 + uu * 5 + i; }
                    Vout[(size_t)e * 576 + col] = s;
                }
                if (tid < 64) Vout[(size_t)e * 576 + tid] = 0.f;
            }
        }
        // ---- C: scalar MLP, batched over 8 edges ----
        __syncthreads();
        if (tid < 64) {
            float acc[8] = {0, 0, 0, 0, 0, 0, 0, 0};
            for (int k4 = 0; k4 < 80; k4++) {
                float4 w = *(const float4*)&g_W1T[k4 * 256 + tid * 4];
#pragma unroll
                for (int b = 0; b < 8; b++) {
                    float4 xv = *(const float4*)&x2b[b * 320 + k4 * 4];
                    acc[b] += w.x * xv.x + w.y * xv.y + w.z * xv.z + w.w * xv.w;
                }
            }
#pragma unroll
            for (int b = 0; b < 8; b++) h1b[b * 64 + tid] = silu_n(acc[b] * 0.05590169943749474f, silu_c);
        }
        __syncthreads();
        if (tid < 64) {
            float acc[8] = {0, 0, 0, 0, 0, 0, 0, 0};
#pragma unroll
            for (int k4 = 0; k4 < 16; k4++) {
                float4 w = *(const float4*)&g_W2T[k4 * 256 + tid * 4];
#pragma unroll
                for (int b = 0; b < 8; b++) {
                    float4 hv = *(const float4*)&h1b[b * 64 + k4 * 4];
                    acc[b] += w.x * hv.x + w.y * hv.y + w.z * hv.z + w.w * hv.w;
                }
            }
#pragma unroll
            for (int b = 0; b < 8; b++) h2b[b * 64 + tid] = silu_n(acc[b] * 0.125f, silu_c);
        }
        __syncthreads();
        if (tid < 64) {
            float acc[8] = {0, 0, 0, 0, 0, 0, 0, 0};
#pragma unroll
            for (int k4 = 0; k4 < 16; k4++) {
                float4 w = *(const float4*)&g_W3T[k4 * 256 + tid * 4];
#pragma unroll
                for (int b = 0; b < 8; b++) {
                    float4 hv = *(const float4*)&h2b[b * 64 + k4 * 4];
                    acc[b] += w.x * hv.x + w.y * hv.y + w.z * hv.z + w.w * hv.w;
                }
            }
#pragma unroll
            for (int b = 0; b < 8; b++)
                xout[(size_t)(e0 + b) * 64 + tid] = envb[b] * acc[b] * 0.125f;
        }
    }
}

// ---------------------------------------------------------------------------
extern "C" void kernel_launch(void* const* d_in, const int* in_sizes, int n_in,
                              void* d_out, int out_size) {
    const float* vectors = (const float*)d_in[0];
    const float* x       = (const float*)d_in[1];
    const float* V       = (const float*)d_in[2];
    const int*   senders = (const int*)d_in[3];
    const float* W0      = (const float*)d_in[4];
    const float* W1      = (const float*)d_in[5];
    const float* W2      = (const float*)d_in[6];
    const float* W3      = (const float*)d_in[7];
    const float* Wl1     = (const float*)d_in[8];
    const float* Wl2     = (const float*)d_in[9];
    float* xout = (float*)d_out;
    float* Vout = xout + (size_t)32768 * 64;

    cudaFuncSetAttribute(k2_main, cudaFuncAttributeMaxDynamicSharedMemorySize, K2_SMEM);

    init_consts_kernel<<<1, 256>>>();
    prep_weights_kernel<<<144, 256>>>(W0, W1, W2, W3);
    zero_nodesum_kernel<<<2048, 256>>>();
    k1_scatter<<<8192, 256>>>(vectors, x, senders);
    k2_main<<<1024, 256, K2_SMEM>>>(vectors, x, V, senders, Wl1, Wl2, xout, Vout);
}

// round 4
// speedup vs baseline: 2.4177x; 2.4177x over previous
#include <cuda_runtime.h>
#include <math.h>

#define NNODES 2048
#define NEDGES 32768

__constant__ float c_fact[16] = {
    1.f, 1.f, 2.f, 6.f, 24.f, 120.f, 720.f, 5040.f, 40320.f, 362880.f,
    3628800.f, 39916800.f, 479001600.f, 6227020800.f, 87178291200.f, 1307674368000.f};

struct DevConsts {
    float cg[576];
    float rec1[45];
    float rec2[105];
    float sh_s0, sh_s1, silu_c;
};
__device__ DevConsts g_c;

__device__ __align__(16) float g_node_sum[NNODES * 1024];
__device__ __align__(16) float g_W0T[8192];
__device__ __align__(16) float g_Wg1[20480];
__device__ __align__(16) float g_Wg2[20480];
__device__ __align__(16) float g_W1r[20480];
__device__ __align__(16) float g_vbuf[(size_t)8 * NEDGES * 320];
__device__ __align__(16) float g_x2buf[(size_t)NEDGES * 320];
__device__ __align__(16) float g_h1[(size_t)NEDGES * 64];

__device__ __forceinline__ float to_tf32(float x) {
    unsigned r;
    asm("cvt.rna.tf32.f32 %0, %1;" : "=r"(r) : "f"(x));
    return __uint_as_float(r);
}

// ---------------------------------------------------------------------------
// device-side e3nn constants
// ---------------------------------------------------------------------------
__device__ float su2_cg(int j1, int m1, int j2, int m2, int j3, int m3) {
    if (m1 + m2 != m3) return 0.f;
    int vmin = max(max(-j1 + j2 + m3, -j1 + m1), 0);
    int vmax = min(min(j2 + j3 + m1, j3 - j1 + j2), j3 + m3);
    float c = sqrtf((2.f * j3 + 1.f) * c_fact[j3 + j1 - j2] * c_fact[j3 - j1 + j2] *
                    c_fact[j1 + j2 - j3] / c_fact[j1 + j2 + j3 + 1] *
                    c_fact[j3 + m3] * c_fact[j3 - m3] /
                    (c_fact[j1 + m1] * c_fact[j1 - m1] * c_fact[j2 + m2] * c_fact[j2 - m2]));
    float s = 0.f;
    for (int v = vmin; v <= vmax; v++) {
        float t = c_fact[j2 + j3 + m1 - v] * c_fact[j1 - m1 + v] /
                  (c_fact[v] * c_fact[j3 - j1 + j2 - v] * c_fact[j3 + m3 - v] *
                   c_fact[v + j1 - j2 - m3]);
        s += ((v + j2 + m2) & 1) ? -t : t;
    }
    return c * s;
}

__device__ void build_q(int l, float2* q) {
    int d = 2 * l + 1;
    for (int i = 0; i < d * d; i++) q[i] = make_float2(0.f, 0.f);
    const float r = 0.7071067811865476f;
    for (int m = -l; m < 0; m++) {
        q[(l + m) * d + (l - m)] = make_float2(r, 0.f);
        q[(l + m) * d + (l + m)] = make_float2(0.f, -r);
    }
    q[l * d + l] = make_float2(1.f, 0.f);
    for (int m = 1; m <= l; m++) {
        float sg = (m & 1) ? -1.f : 1.f;
        q[(l + m) * d + (l + m)] = make_float2(sg * r, 0.f);
        q[(l + m) * d + (l - m)] = make_float2(0.f, sg * r);
    }
    float2 ph;
    switch (l & 3) {
        case 0: ph = make_float2(1.f, 0.f); break;
        case 1: ph = make_float2(0.f, -1.f); break;
        case 2: ph = make_float2(-1.f, 0.f); break;
        default: ph = make_float2(0.f, 1.f); break;
    }
    for (int i = 0; i < d * d; i++) {
        float2 a = q[i];
        q[i] = make_float2(a.x * ph.x - a.y * ph.y, a.x * ph.y + a.y * ph.x);
    }
}

__global__ void init_consts_kernel() {
    __shared__ float Cr[125];
    __shared__ float outs[125];
    __shared__ float2 q1s[49], q2s[49], q3s[49];
    __shared__ float red[256];
    int tid = threadIdx.x;
    const int NT = 14;
    const int tl1[NT] = {0, 1, 2, 0, 1, 1, 2, 3, 0, 1, 2, 2, 3, 2};
    const int tl2[NT] = {0, 1, 2, 1, 0, 2, 1, 2, 2, 1, 0, 2, 1, 1};
    const int tl3[NT] = {0, 0, 0, 1, 1, 1, 1, 1, 2, 2, 2, 2, 2, 3};
    const int toff[NT] = {0, 1, 10, 35, 44, 53, 98, 143, 248, 273, 318, 343, 468, 0};

    for (int t = 0; t < NT; t++) {
        int l1 = tl1[t], l2 = tl2[t], l3 = tl3[t];
        int d1 = 2 * l1 + 1, d2 = 2 * l2 + 1, d3 = 2 * l3 + 1;
        int sz = d1 * d2 * d3;
        for (int idx = tid; idx < sz; idx += blockDim.x) {
            int i = idx / (d2 * d3), rr = idx % (d2 * d3), k = rr / d3, m = rr % d3;
            Cr[idx] = su2_cg(l1, i - l1, l2, k - l2, l3, m - l3);
        }
        if (tid == 0) build_q(l1, q1s);
        else if (tid == 1) build_q(l2, q2s);
        else if (tid == 2) build_q(l3, q3s);
        __syncthreads();
        float ss = 0.f;
        for (int idx = tid; idx < sz; idx += blockDim.x) {
            int j = idx / (d2 * d3), rr = idx % (d2 * d3), lc = rr / d3, n = rr % d3;
            float re = 0.f;
            for (int i = 0; i < d1; i++) {
                float2 a = q1s[i * d1 + j];
                for (int k = 0; k < d2; k++) {
                    float2 b = q2s[k * d2 + lc];
                    float abr = a.x * b.x - a.y * b.y;
                    float abi = a.x * b.y + a.y * b.x;
                    for (int m = 0; m < d3; m++) {
                        float cv = Cr[(i * d2 + k) * d3 + m];
                        if (cv == 0.f) continue;
                        float2 g = q3s[m * d3 + n];
                        re += cv * (abr * g.x + abi * g.y);
                    }
                }
            }
            outs[idx] = re;
            ss += re * re;
        }
        red[tid] = ss;
        __syncthreads();
        for (int st = 128; st > 0; st >>= 1) {
            if (tid < st) red[tid] += red[tid + st];
            __syncthreads();
        }
        float inv = rsqrtf(red[0]);
        for (int idx = tid; idx < sz; idx += blockDim.x) {
            float v = outs[idx] * inv;
            if (t == 13) g_c.rec2[idx] = v;
            else {
                g_c.cg[toff[t] + idx] = v;
                if (l1 == 1 && l2 == 1 && l3 == 2) g_c.rec1[idx] = v;
            }
        }
        __syncthreads();
    }

    if (tid == 0) {
        float n0 = 0.3f, n1 = 0.5f, n2 = 0.81f;
        float inv = rsqrtf(n0 * n0 + n1 * n1 + n2 * n2);
        float ny[3] = {n1 * inv, n2 * inv, n0 * inv};
        float Y1[3];
        for (int i = 0; i < 3; i++) Y1[i] = 1.7320508075688772f * ny[i];
        float A[5] = {0, 0, 0, 0, 0};
        for (int i = 0; i < 3; i++)
            for (int j = 0; j < 3; j++) {
                float tt = Y1[i] * ny[j];
                for (int k = 0; k < 5; k++) A[k] += tt * g_c.rec1[(i * 3 + j) * 5 + k];
            }
        float na = 0.f;
        for (int k = 0; k < 5; k++) na += A[k] * A[k];
        float s0 = sqrtf(5.f) * rsqrtf(na);
        g_c.sh_s0 = s0;
        float Y2[5];
        for (int k = 0; k < 5; k++) Y2[k] = A[k] * s0;
        float B[7] = {0, 0, 0, 0, 0, 0, 0};
        for (int i = 0; i < 5; i++)
            for (int j = 0; j < 3; j++) {
                float tt = Y2[i] * ny[j];
                for (int k = 0; k < 7; k++) B[k] += tt * g_c.rec2[(i * 3 + j) * 7 + k];
            }
        float nb = 0.f;
        for (int k = 0; k < 7; k++) nb += B[k] * B[k];
        g_c.sh_s1 = sqrtf(7.f) * rsqrtf(nb);
    }

    float part = 0.f;
    for (int i = tid; i < 20001; i += blockDim.x) {
        float z = -12.f + 24.f * (float)i / 20000.f;
        float s = z / (1.f + expf(-z));
        float phi = expf(-0.5f * z * z) * 0.3989422804014327f;
        float w = (i == 0 || i == 20000) ? 0.5f : 1.f;
        part += w * s * s * phi;
    }
    red[tid] = part;
    __syncthreads();
    for (int st = 128; st > 0; st >>= 1) {
        if (tid < st) red[tid] += red[tid + st];
        __syncthreads();
    }
    if (tid == 0) g_c.silu_c = rsqrtf(red[0] * (24.f / 20000.f));
}

// ---------------------------------------------------------------------------
__global__ void zero_nodesum_kernel() {
    int i = blockIdx.x * blockDim.x + threadIdx.x;
    ((float4*)g_node_sum)[i] = make_float4(0.f, 0.f, 0.f, 0.f);
}

__global__ void prep_weights_kernel(const float* __restrict__ W0, const float* __restrict__ W1,
                                    const float* __restrict__ Wl1, const float* __restrict__ Wl2) {
    int i = blockIdx.x * blockDim.x + threadIdx.x;
    if (i < 8192) {
        int k4 = i >> 8, rm = i & 255, u = rm >> 2, r = rm & 3;
        g_W0T[i] = W0[(k4 * 4 + r) * 64 + u];
        return;
    }
    i -= 8192;
    if (i < 20480) { g_W1r[i] = to_tf32(W1[i]); return; }
    i -= 20480;
    if (i < 20480) {
        int mp = i >> 6, u = i & 63, p = mp >> 6, um = mp & 63;
        g_Wg1[i] = to_tf32(Wl1[(um * 5 + p) * 64 + u]);
        return;
    }
    i -= 20480;
    if (i < 20480) {
        int mp = i >> 6, u = i & 63, p = mp >> 6, um = mp & 63;
        g_Wg2[i] = to_tf32(Wl2[(um * 5 + p) * 64 + u]);
    }
}

// ---------------------------------------------------------------------------
// K1: w = x@W0/sqrt(128), Y via recursion, scatter w⊗Y into g_node_sum
// ---------------------------------------------------------------------------
__global__ void __launch_bounds__(256) k1_scatter(const float* __restrict__ vectors,
                                                  const float* __restrict__ x,
                                                  const int* __restrict__ senders) {
    __shared__ __align__(16) float xs[4][128];
    __shared__ float ws[4][64];
    __shared__ float Ys[4][16];
    int tid = threadIdx.x, sub = tid >> 6, ut = tid & 63;
    int e = blockIdx.x * 4 + sub;
    xs[sub][ut] = x[(size_t)e * 128 + ut];
    xs[sub][ut + 64] = x[(size_t)e * 128 + 64 + ut];
    __syncthreads();
    float acc = 0.f;
#pragma unroll
    for (int k4 = 0; k4 < 32; k4++) {
        float4 w = *(const float4*)&g_W0T[k4 * 256 + ut * 4];
        float4 xv = ((const float4*)xs[sub])[k4];
        acc += w.x * xv.x + w.y * xv.y + w.z * xv.z + w.w * xv.w;
    }
    ws[sub][ut] = acc * 0.08838834764831845f;
    if (ut == 0) {
        float vx = vectors[3 * e], vy = vectors[3 * e + 1], vz = vectors[3 * e + 2];
        float inv = rsqrtf(vx * vx + vy * vy + vz * vz);
        float ny[3] = {vy * inv, vz * inv, vx * inv};
        Ys[sub][0] = 1.f;
        float Y1[3];
#pragma unroll
        for (int i = 0; i < 3; i++) { Y1[i] = 1.7320508075688772f * ny[i]; Ys[sub][1 + i] = Y1[i]; }
        float Y2[5] = {0, 0, 0, 0, 0};
        for (int i = 0; i < 3; i++)
            for (int j = 0; j < 3; j++) {
                float t = Y1[i] * ny[j];
#pragma unroll
                for (int k = 0; k < 5; k++) Y2[k] += t * g_c.rec1[(i * 3 + j) * 5 + k];
            }
        float s0 = g_c.sh_s0;
#pragma unroll
        for (int k = 0; k < 5; k++) { Y2[k] *= s0; Ys[sub][4 + k] = Y2[k]; }
        float Y3[7] = {0, 0, 0, 0, 0, 0, 0};
        for (int i = 0; i < 5; i++)
            for (int j = 0; j < 3; j++) {
                float t = Y2[i] * ny[j];
#pragma unroll
                for (int k = 0; k < 7; k++) Y3[k] += t * g_c.rec2[(i * 3 + j) * 7 + k];
            }
        float s1 = g_c.sh_s1;
#pragma unroll
        for (int k = 0; k < 7; k++) Ys[sub][9 + k] = Y3[k] * s1;
    }
    __syncthreads();
    int s = senders[e];
    float* np = g_node_sum + (size_t)s * 1024;
#pragma unroll
    for (int g = 0; g < 4; g++) {
        int base = ut * 4 + g * 256;
        int uu = base >> 4, i0 = base & 15;
        float w = ws[sub][uu];
        atomicAdd((float4*)(np + base),
                  make_float4(w * Ys[sub][i0], w * Ys[sub][i0 + 1], w * Ys[sub][i0 + 2], w * Ys[sub][i0 + 3]));
    }
}

// ---------------------------------------------------------------------------
// K2a: tensor product per edge, write vbuf (i-major) + x2buf, tf32-rounded
// ---------------------------------------------------------------------------
template <int L1, int L2, int L3, int OFF>
__device__ __forceinline__ void tp_acc(const float* __restrict__ cgs, const float* wr,
                                       const float* vr, float* dst) {
    const int d1 = 2 * L1 + 1, d2 = 2 * L2 + 1, d3 = 2 * L3 + 1;
#pragma unroll
    for (int k = 0; k < d3; k++) dst[k] = 0.f;
#pragma unroll
    for (int i = 0; i < d1; i++) {
#pragma unroll
        for (int j = 0; j < d2; j++) {
            float t = wr[L1 * L1 + i] * vr[L2 * L2 + j];
#pragma unroll
            for (int k = 0; k < d3; k++) dst[k] += t * cgs[OFF + (i * d2 + j) * d3 + k];
        }
    }
}

__global__ void __launch_bounds__(256) k2a_tp(const float* __restrict__ x,
                                              const float* __restrict__ V,
                                              const int* __restrict__ senders) {
    __shared__ float cgs[576];
    __shared__ float wYs[4][64 * 17];
    __shared__ __align__(16) float Vs[4][576];
    __shared__ int sends[4];
    int tid = threadIdx.x;
    int eb = blockIdx.x * 4;
    for (int t = tid; t < 573; t += 256) cgs[t] = g_c.cg[t];
    if (tid < 4) sends[tid] = senders[eb + tid];
    __syncthreads();
    for (int t = tid; t < 1024; t += 256) {
        int sub = t >> 8, r = t & 255;
        float4 v = ((const float4*)(g_node_sum + (size_t)sends[sub] * 1024))[r];
        int uu = r >> 2, j0 = (r & 3) * 4;
        float* d = &wYs[sub][uu * 17 + j0];
        d[0] = v.x * 0.25f; d[1] = v.y * 0.25f; d[2] = v.z * 0.25f; d[3] = v.w * 0.25f;
    }
    for (int t = tid; t < 576; t += 256) {
        int sub = t / 144, r = t - sub * 144;
        ((float4*)Vs[sub])[r] = ((const float4*)(V + (size_t)(eb + sub) * 576))[r];
    }
    for (int t = tid; t < 128; t += 256) {
        int sub = t >> 5, r = t & 31;
        float4 xv = ((const float4*)(x + (size_t)(eb + sub) * 128))[r];
        xv.x = to_tf32(xv.x); xv.y = to_tf32(xv.y); xv.z = to_tf32(xv.z); xv.w = to_tf32(xv.w);
        ((float4*)(g_x2buf + (size_t)(eb + sub) * 320))[r] = xv;
    }
    __syncthreads();
    int sub = tid >> 6, u = tid & 63;
    int e = eb + sub;
    float wr[16], vr[9];
#pragma unroll
    for (int j = 0; j < 16; j++) wr[j] = wYs[sub][u * 17 + j];
#pragma unroll
    for (int j = 0; j < 9; j++) vr[j] = Vs[sub][u * 9 + j];

    float s0o[3], o1[5][3], o2[5][5];
    tp_acc<0, 0, 0, 0>(cgs, wr, vr, &s0o[0]);
    tp_acc<1, 1, 0, 1>(cgs, wr, vr, &s0o[1]);
    tp_acc<2, 2, 0, 10>(cgs, wr, vr, &s0o[2]);
    tp_acc<0, 1, 1, 35>(cgs, wr, vr, o1[0]);
    tp_acc<1, 0, 1, 44>(cgs, wr, vr, o1[1]);
    tp_acc<1, 2, 1, 53>(cgs, wr, vr, o1[2]);
    tp_acc<2, 1, 1, 98>(cgs, wr, vr, o1[3]);
    tp_acc<3, 2, 1, 143>(cgs, wr, vr, o1[4]);
    tp_acc<0, 2, 2, 248>(cgs, wr, vr, o2[0]);
    tp_acc<1, 1, 2, 273>(cgs, wr, vr, o2[1]);
    tp_acc<2, 0, 2, 318>(cgs, wr, vr, o2[2]);
    tp_acc<2, 2, 2, 343>(cgs, wr, vr, o2[3]);
    tp_acc<3, 1, 2, 468>(cgs, wr, vr, o2[4]);

    const float R3 = 1.7320508075688772f, R5 = 2.2360679774997896f;
    float* x2p = g_x2buf + (size_t)e * 320 + 128 + u * 3;
    x2p[0] = to_tf32(s0o[0]); x2p[1] = to_tf32(s0o[1]); x2p[2] = to_tf32(s0o[2]);
#pragma unroll
    for (int i = 0; i < 3; i++)
#pragma unroll
        for (int p = 0; p < 5; p++)
            g_vbuf[((size_t)i * NEDGES + e) * 320 + p * 64 + u] = to_tf32(R3 * o1[p][i]);
#pragma unroll
    for (int i = 0; i < 5; i++)
#pragma unroll
        for (int p = 0; p < 5; p++)
            g_vbuf[((size_t)(3 + i) * NEDGES + e) * 320 + p * 64 + u] = to_tf32(R5 * o2[p][i]);
}

// ---------------------------------------------------------------------------
// K_gemm: 9 slices of [32768x320]@[320x64] via tf32 mma.sync, fused epilogues
// ---------------------------------------------------------------------------
__global__ void __launch_bounds__(256) k_gemm(float* __restrict__ Vout) {
    __shared__ __align__(16) float As[128 * 36];
    __shared__ __align__(16) float Bs[32 * 72];
    int tid = threadIdx.x, s = blockIdx.y;
    int e0 = blockIdx.x * 128;
    const float* Ab = (s < 8) ? g_vbuf + (size_t)s * NEDGES * 320 : g_x2buf;
    const float* Bm = (s < 3) ? g_Wg1 : (s < 8 ? g_Wg2 : g_W1r);
    int lane = tid & 31, warp = tid >> 5;
    int wm = warp & 3, wn = warp >> 2;
    int g = lane >> 2, tig = lane & 3;
    float acc[2][4][4];
#pragma unroll
    for (int a = 0; a < 2; a++)
#pragma unroll
        for (int b = 0; b < 4; b++)
#pragma unroll
            for (int c = 0; c < 4; c++) acc[a][b][c] = 0.f;

    for (int kc = 0; kc < 10; kc++) {
        __syncthreads();
        int k0 = kc * 32;
#pragma unroll
        for (int i = 0; i < 4; i++) {
            int idx = tid + i * 256;
            int row = idx >> 3, c4 = idx & 7;
            float4 v = ((const float4*)(Ab + (size_t)(e0 + row) * 320 + k0))[c4];
            *(float4*)&As[row * 36 + c4 * 4] = v;
        }
#pragma unroll
        for (int i = 0; i < 2; i++) {
            int idx = tid + i * 256;
            int k = idx >> 4, n4 = idx & 15;
            float4 v = ((const float4*)(Bm + (size_t)(k0 + k) * 64))[n4];
            *(float4*)&Bs[k * 72 + n4 * 4] = v;
        }
        __syncthreads();
#pragma unroll
        for (int ks = 0; ks < 4; ks++) {
            int kb = ks * 8;
            unsigned af[2][4], bf[4][2];
#pragma unroll
            for (int tm = 0; tm < 2; tm++) {
                int r = wm * 32 + tm * 16 + g;
                af[tm][0] = __float_as_uint(As[r * 36 + kb + tig]);
                af[tm][1] = __float_as_uint(As[(r + 8) * 36 + kb + tig]);
                af[tm][2] = __float_as_uint(As[r * 36 + kb + tig + 4]);
                af[tm][3] = __float_as_uint(As[(r + 8) * 36 + kb + tig + 4]);
            }
#pragma unroll
            for (int tn = 0; tn < 4; tn++) {
                int c = wn * 32 + tn * 8 + g;
                bf[tn][0] = __float_as_uint(Bs[(kb + tig) * 72 + c]);
                bf[tn][1] = __float_as_uint(Bs[(kb + tig + 4) * 72 + c]);
            }
#pragma unroll
            for (int tm = 0; tm < 2; tm++)
#pragma unroll
                for (int tn = 0; tn < 4; tn++) {
                    asm volatile(
                        "mma.sync.aligned.m16n8k8.row.col.f32.tf32.tf32.f32 "
                        "{%0,%1,%2,%3}, {%4,%5,%6,%7}, {%8,%9}, {%0,%1,%2,%3};\n"
                        : "+f"(acc[tm][tn][0]), "+f"(acc[tm][tn][1]),
                          "+f"(acc[tm][tn][2]), "+f"(acc[tm][tn][3])
                        : "r"(af[tm][0]), "r"(af[tm][1]), "r"(af[tm][2]), "r"(af[tm][3]),
                          "r"(bf[tn][0]), "r"(bf[tn][1]));
                }
        }
    }

    const float scale = 0.05590169943749474f; // 1/sqrt(320)
    float silu_c = g_c.silu_c;
#pragma unroll
    for (int tm = 0; tm < 2; tm++)
#pragma unroll
        for (int tn = 0; tn < 4; tn++)
#pragma unroll
            for (int q = 0; q < 4; q++) {
                int r = wm * 32 + tm * 16 + g + ((q >= 2) ? 8 : 0);
                int u = wn * 32 + tn * 8 + 2 * tig + (q & 1);
                int e = e0 + r;
                float v = acc[tm][tn][q] * scale;
                if (s < 3) Vout[(size_t)e * 576 + 64 + u * 3 + s] = v;
                else if (s < 8) Vout[(size_t)e * 576 + 256 + u * 5 + (s - 3)] = v;
                else g_h1[(size_t)e * 64 + u] = silu_c * v / (1.f + __expf(-v));
            }
}

// ---------------------------------------------------------------------------
// K3: MLP layers 2+3, envelope, xout, zero Vout scalar block
// ---------------------------------------------------------------------------
__global__ void __launch_bounds__(256) k3_mlp(const float* __restrict__ vectors,
                                              const float* __restrict__ W2,
                                              const float* __restrict__ W3,
                                              float* __restrict__ xout,
                                              float* __restrict__ Vout) {
    __shared__ float h1s[4][64], h2s[4][64];
    int tid = threadIdx.x, sub = tid >> 6, u = tid & 63;
    int e = blockIdx.x * 4 + sub;
    h1s[sub][u] = g_h1[(size_t)e * 64 + u];
    float silu_c = g_c.silu_c;
    __syncthreads();
    float acc = 0.f;
#pragma unroll 8
    for (int k = 0; k < 64; k++) acc += h1s[sub][k] * W2[k * 64 + u];
    float z = acc * 0.125f;
    h2s[sub][u] = silu_c * z / (1.f + __expf(-z));
    __syncthreads();
    acc = 0.f;
#pragma unroll 8
    for (int k = 0; k < 64; k++) acc += h2s[sub][k] * W3[k * 64 + u];
    float vx = vectors[3 * e], vy = vectors[3 * e + 1], vz = vectors[3 * e + 2];
    float d = sqrtf(vx * vx + vy * vy + vz * vz);
    float d3 = d * d * d, d6 = d3 * d3;
    float env = (d < 1.f) ? 1.f + d6 * (-28.f + d * (48.f - 21.f * d)) : 0.f;
    xout[(size_t)e * 64 + u] = env * acc * 0.125f;
    Vout[(size_t)e * 576 + u] = 0.f;
}

// ---------------------------------------------------------------------------
extern "C" void kernel_launch(void* const* d_in, const int* in_sizes, int n_in,
                              void* d_out, int out_size) {
    const float* vectors = (const float*)d_in[0];
    const float* x       = (const float*)d_in[1];
    const float* V       = (const float*)d_in[2];
    const int*   senders = (const int*)d_in[3];
    const float* W0      = (const float*)d_in[4];
    const float* W1      = (const float*)d_in[5];
    const float* W2      = (const float*)d_in[6];
    const float* W3      = (const float*)d_in[7];
    const float* Wl1     = (const float*)d_in[8];
    const float* Wl2     = (const float*)d_in[9];
    float* xout = (float*)d_out;
    float* Vout = xout + (size_t)NEDGES * 64;

    init_consts_kernel<<<1, 256>>>();
    prep_weights_kernel<<<272, 256>>>(W0, W1, Wl1, Wl2);
    zero_nodesum_kernel<<<2048, 256>>>();
    k1_scatter<<<8192, 256>>>(vectors, x, senders);
    k2a_tp<<<8192, 256>>>(x, V, senders);
    dim3 gg(256, 9);
    k_gemm<<<gg, 256>>>(Vout);
    k3_mlp<<<8192, 256>>>(vectors, W2, W3, xout, Vout);
}